// round 8
// baseline (speedup 1.0000x reference)
#include <cuda_runtime.h>
#include <cstdint>

#define B_DIM  1024
#define H_DIM  2048
#define KTOT   6144
#define NTOT   8192
#define NCH    48
#define T_CH   27          // tensor chunks 0..26  (x:0-15, hi:16-26)
#define D_CH   21          // dp4a chunks 27..47   (hi:27-31 -> acc2a, lo:32-47 -> acc2b)
#define CHUNK_BYTES 20480  // A 16KB + B 4KB
#define T_BASE 0
#define D_BASE (4 * CHUNK_BYTES)            // 81920
#define SMEM_BYTES (8 * CHUNK_BYTES)        // 163840

// Exchange buffer lives INSIDE the dp4a group's pipeline region: by the time
// the dp4a group writes it (after its own wait_group 0 + bar.sync 2), those
// stage buffers are dead. It must NOT overlap the tensor region, which is
// still live (R6 bug: EXCH_OFF=0 corrupted in-flight tensor chunks).
#define EXCH_OFF D_BASE                      // 128 slots x 68 ints = 34816 B
#define CX_OFF   0                           // tensor region, used after join
#define H_OFF    (CX_OFF + 4608)
#define C_OFF    (H_OFF + 4608)

// h scale: S = 256*127/5; v = round(hx*S) in [-32511,32511]; v = hi*256 + lo
#define SCALE_H 6502.4f
#define VCLAMP  32511.0f

__device__ __align__(256) int8_t g_A[(size_t)B_DIM * KTOT];
__device__ __align__(256) int8_t g_B[(size_t)NTOT * KTOT];
__device__ float g_bias[NTOT];

// ------------------------------- helpers ----------------------------------

__device__ __forceinline__ uint32_t smem_u32(const void* p) {
    uint32_t a;
    asm("{ .reg .u64 t; cvta.to.shared.u64 t, %1; cvt.u32.u64 %0, t; }"
        : "=r"(a) : "l"(p));
    return a;
}

__device__ __forceinline__ float fq8(float v) {
    float q = rintf(v * 127.0f);
    q = fminf(127.0f, fmaxf(-127.0f, q));
    return q * (1.0f / 127.0f);
}

__device__ __forceinline__ float sigm_(float x) {
    return 1.0f / (1.0f + expf(-x));
}

__device__ __forceinline__ float tanh_(float x) {
    float e = expf(-2.0f * fabsf(x));
    return copysignf((1.0f - e) / (1.0f + e), x);
}

__device__ __forceinline__ signed char q127(float w) {
    float q = rintf(w * 127.0f);
    q = fminf(127.0f, fmaxf(-127.0f, q));
    return (signed char)(int)q;
}

// ------------------------------ prep kernels ------------------------------

__global__ void prep_A(const float* __restrict__ x, const float* __restrict__ hx) {
    const int b = blockIdx.y;
    const int c4 = blockIdx.x * 256 + threadIdx.x;      // 0..511
    const int k = c4 << 2;
    const float4 xv = *reinterpret_cast<const float4*>(x + (size_t)b * 2048 + k);
    const float4 hv = *reinterpret_cast<const float4*>(hx + (size_t)b * 2048 + k);
    const float* xf = reinterpret_cast<const float*>(&xv);
    const float* hf = reinterpret_cast<const float*>(&hv);
    char4 xq, hiq, loq;
    signed char* xp = reinterpret_cast<signed char*>(&xq);
    signed char* hp = reinterpret_cast<signed char*>(&hiq);
    signed char* lp = reinterpret_cast<signed char*>(&loq);
#pragma unroll
    for (int j = 0; j < 4; ++j) {
        xp[j] = q127(xf[j]);
        float vf = rintf(hf[j] * SCALE_H);
        vf = fminf(VCLAMP, fmaxf(-VCLAMP, vf));
        int v = (int)vf;
        int hi = (v + 128) >> 8;            // hi in [-127,127]
        int lo = v - (hi << 8);             // lo in [-128,127]
        hp[j] = (signed char)hi;
        lp[j] = (signed char)lo;
    }
    size_t base = (size_t)b * KTOT + k;
    *reinterpret_cast<char4*>(g_A + base)        = xq;
    *reinterpret_cast<char4*>(g_A + base + 2048) = hiq;
    *reinterpret_cast<char4*>(g_A + base + 4096) = loq;
}

// B row r=4u+g from orig row g*2048+u: [0,2048) wxI ; [2048,4096) whI*5 ; [4096,6144) whI
__global__ void prep_W(const float* __restrict__ wx, const float* __restrict__ wh) {
    const int r = blockIdx.y;
    const int c4 = blockIdx.x * 256 + threadIdx.x;      // 0..1535
    const int u = r >> 2, g = r & 3;
    const size_t orig = (size_t)(g * H_DIM + u) * 2048;
    char4 outv;
    signed char* op = reinterpret_cast<signed char*>(&outv);
    if (c4 < 512) {
        const float4 wv = *reinterpret_cast<const float4*>(wx + orig + (c4 << 2));
        const float* wf = reinterpret_cast<const float*>(&wv);
#pragma unroll
        for (int j = 0; j < 4; ++j) op[j] = q127(wf[j]);
    } else if (c4 < 1024) {
        const float4 wv = *reinterpret_cast<const float4*>(wh + orig + ((c4 - 512) << 2));
        const float* wf = reinterpret_cast<const float*>(&wv);
#pragma unroll
        for (int j = 0; j < 4; ++j) op[j] = (signed char)(5 * (int)q127(wf[j]));
    } else {
        const float4 wv = *reinterpret_cast<const float4*>(wh + orig + ((c4 - 1024) << 2));
        const float* wf = reinterpret_cast<const float*>(&wv);
#pragma unroll
        for (int j = 0; j < 4; ++j) op[j] = q127(wf[j]);
    }
    *reinterpret_cast<char4*>(g_B + (size_t)r * KTOT + (c4 << 2)) = outv;
}

__global__ void prep_bias(const float* __restrict__ bx, const float* __restrict__ bh) {
    int r = blockIdx.x * 256 + threadIdx.x;
    if (r >= NTOT) return;
    int u = r >> 2, g = r & 3;
    int orig = g * H_DIM + u;
    g_bias[r] = bx[orig] + bh[orig];
}

// ------------------------------- GEMM kernel ------------------------------
// CTA: 128(M) x 32(N), 256 threads, 1 CTA/SM.
// Warps 0-3: tensor group (mma.s8, chunks 0..26, acc1).
// Warps 4-7: dp4a group (chunks 27..47, acc2a/acc2b).

__device__ __forceinline__ void prefetch_chunk(uint32_t base, int stage, int chunk,
                                               int m0, int n0, int gt) {
    const int koff = chunk << 7;
    const uint32_t sbase = base + (uint32_t)stage * CHUNK_BYTES;
#pragma unroll
    for (int p = 0; p < 10; ++p) {
        const int idx = p * 128 + gt;       // 0..1279 ; <1024 A, else B
        const bool isA = idx < 1024;
        const int v = isA ? idx : idx - 1024;
        const int row = v >> 3;
        const int q = v & 7;
        const uint32_t dst = sbase + (isA ? 0u : 16384u)
                           + (uint32_t)(row << 7)
                           + (uint32_t)((q ^ (row & 7)) << 4);
        const int8_t* src = isA
            ? g_A + (size_t)(m0 + row) * KTOT + koff + (q << 4)
            : g_B + (size_t)(n0 + row) * KTOT + koff + (q << 4);
        asm volatile("cp.async.cg.shared.global [%0], [%1], 16;"
                     :: "r"(dst), "l"(src));
    }
}

#define COMPUTE_CHUNK(ACC, SA)                                                 \
  {                                                                            \
    const uint32_t sA = (SA);                                                  \
    const uint32_t sB = sA + 16384u;                                           \
    _Pragma("unroll")                                                          \
    for (int ks = 0; ks < 4; ++ks) {                                           \
      uint32_t a[4][4], b[4];                                                  \
      _Pragma("unroll")                                                        \
      for (int mf = 0; mf < 4; ++mf) {                                         \
        const int row = wm * 64 + mf * 16 + rsel;                              \
        const uint32_t ad = sA + (uint32_t)(row << 7)                          \
                          + (uint32_t)((((ks * 2 + khalf)) ^ (row & 7)) << 4); \
        asm volatile(                                                          \
          "ldmatrix.sync.aligned.m8n8.x4.shared.b16 {%0,%1,%2,%3}, [%4];"      \
          : "=r"(a[mf][0]), "=r"(a[mf][1]), "=r"(a[mf][2]), "=r"(a[mf][3])     \
          : "r"(ad));                                                          \
      }                                                                        \
      {                                                                        \
        const int row = wn * 16 + rsel;                                        \
        const uint32_t bd = sB + (uint32_t)(row << 7)                          \
                          + (uint32_t)((((ks * 2 + khalf)) ^ (row & 7)) << 4); \
        asm volatile(                                                          \
          "ldmatrix.sync.aligned.m8n8.x4.shared.b16 {%0,%1,%2,%3}, [%4];"      \
          : "=r"(b[0]), "=r"(b[1]), "=r"(b[2]), "=r"(b[3])                     \
          : "r"(bd));                                                          \
      }                                                                        \
      _Pragma("unroll")                                                        \
      for (int mf = 0; mf < 4; ++mf) {                                         \
        _Pragma("unroll")                                                      \
        for (int nf = 0; nf < 2; ++nf) {                                       \
          asm volatile(                                                        \
            "mma.sync.aligned.m16n8k32.row.col.s32.s8.s8.s32 "                 \
            "{%0,%1,%2,%3}, {%4,%5,%6,%7}, {%8,%9}, {%0,%1,%2,%3};"            \
            : "+r"(ACC[mf][nf][0]), "+r"(ACC[mf][nf][1]),                      \
              "+r"(ACC[mf][nf][2]), "+r"(ACC[mf][nf][3])                       \
            : "r"(a[mf][0]), "r"(a[mf][1]), "r"(a[mf][2]), "r"(a[mf][3]),      \
              "r"(b[nf]), "r"(b[2 + nf]));                                     \
        }                                                                      \
      }                                                                        \
    }                                                                          \
  }

// dp4a path: bit-identical accumulation in mma c-fragment layout.
#define DP4A_CHUNK(ACC, SA)                                                    \
  {                                                                            \
    const uint32_t sA = (SA);                                                  \
    const uint32_t sB = sA + 16384u;                                           \
    _Pragma("unroll 2")                                                        \
    for (int kk = 0; kk < 8; ++kk) {                                           \
      uint32_t areg[8][4];                                                     \
      _Pragma("unroll")                                                        \
      for (int mf = 0; mf < 4; ++mf) {                                         \
        _Pragma("unroll")                                                      \
        for (int p = 0; p < 2; ++p) {                                          \
          const int row = wm * 64 + mf * 16 + p * 8 + (lane >> 2);             \
          const uint32_t ad = sA + (uint32_t)(row << 7)                        \
                            + (uint32_t)((kk ^ (row & 7)) << 4);               \
          asm volatile("ld.shared.v4.b32 {%0,%1,%2,%3}, [%4];"                 \
            : "=r"(areg[mf * 2 + p][0]), "=r"(areg[mf * 2 + p][1]),            \
              "=r"(areg[mf * 2 + p][2]), "=r"(areg[mf * 2 + p][3])             \
            : "r"(ad));                                                        \
        }                                                                      \
      }                                                                        \
      uint32_t breg[4][4];                                                     \
      _Pragma("unroll")                                                        \
      for (int nf = 0; nf < 2; ++nf) {                                         \
        _Pragma("unroll")                                                      \
        for (int d = 0; d < 2; ++d) {                                          \
          const int col = wn * 16 + nf * 8 + 2 * (lane & 3) + d;               \
          const uint32_t bd = sB + (uint32_t)(col << 7)                        \
                            + (uint32_t)((kk ^ (col & 7)) << 4);               \
          asm volatile("ld.shared.v4.b32 {%0,%1,%2,%3}, [%4];"                 \
            : "=r"(breg[nf * 2 + d][0]), "=r"(breg[nf * 2 + d][1]),            \
              "=r"(breg[nf * 2 + d][2]), "=r"(breg[nf * 2 + d][3])             \
            : "r"(bd));                                                        \
        }                                                                      \
      }                                                                        \
      _Pragma("unroll")                                                        \
      for (int mf = 0; mf < 4; ++mf) {                                         \
        _Pragma("unroll")                                                      \
        for (int nf = 0; nf < 2; ++nf) {                                       \
          _Pragma("unroll")                                                    \
          for (int e = 0; e < 4; ++e) {                                        \
            const int p = e >> 1, d = e & 1;                                   \
            _Pragma("unroll")                                                  \
            for (int w2 = 0; w2 < 4; ++w2)                                     \
              asm volatile("dp4a.s32.s32 %0, %1, %2, %0;"                      \
                : "+r"(ACC[mf][nf][e])                                         \
                : "r"(areg[mf * 2 + p][w2]), "r"(breg[nf * 2 + d][w2]));       \
          }                                                                    \
        }                                                                      \
      }                                                                        \
    }                                                                          \
  }

__global__ __launch_bounds__(256, 1)
void lstm_imma_kernel(const float* __restrict__ cx, float* __restrict__ out) {
    extern __shared__ char smem[];
    const uint32_t sb = smem_u32(smem);
    const int tid = threadIdx.x, lane = tid & 31, wid = tid >> 5;
    const int grp = wid >> 2;               // 0 = tensor, 1 = dp4a
    const int gt = tid & 127;               // index within group
    const int w = wid & 3;
    const int wm = w >> 1, wn = w & 1;
    const int m0 = blockIdx.y << 7, n0 = blockIdx.x << 5;
    const int rsel = lane & 15, khalf = lane >> 4;

    int* exch = reinterpret_cast<int*>(smem + EXCH_OFF);
    float* cx_sm = reinterpret_cast<float*>(smem + CX_OFF);
    float* h_sm = reinterpret_cast<float*>(smem + H_OFF);
    float* c_sm = reinterpret_cast<float*>(smem + C_OFF);

    int acc1[4][2][4];
#pragma unroll
    for (int i = 0; i < 4; ++i)
#pragma unroll
        for (int j = 0; j < 2; ++j)
#pragma unroll
            for (int k = 0; k < 4; ++k) acc1[i][j][k] = 0;

    if (grp == 0) {
        // ---------------- tensor group: chunks 0..T_CH-1 ----------------
        const uint32_t tb = sb + T_BASE;
        prefetch_chunk(tb, 0, 0, m0, n0, gt);
        asm volatile("cp.async.commit_group;");
        prefetch_chunk(tb, 1, 1, m0, n0, gt);
        asm volatile("cp.async.commit_group;");
        prefetch_chunk(tb, 2, 2, m0, n0, gt);
        asm volatile("cp.async.commit_group;");
        for (int j = 0; j < T_CH; ++j) {
            asm volatile("cp.async.wait_group 2;");
            asm volatile("bar.sync 1, 128;" ::: "memory");
            if (j + 3 < T_CH) prefetch_chunk(tb, (j + 3) & 3, j + 3, m0, n0, gt);
            asm volatile("cp.async.commit_group;");
            COMPUTE_CHUNK(acc1, tb + (uint32_t)((j & 3) * CHUNK_BYTES))
        }
        asm volatile("cp.async.wait_group 0;");
    } else {
        // ---------------- dp4a group: chunks T_CH..47 ----------------
        int a2a[4][2][4], a2b[4][2][4];
#pragma unroll
        for (int i = 0; i < 4; ++i)
#pragma unroll
            for (int j = 0; j < 2; ++j)
#pragma unroll
                for (int k = 0; k < 4; ++k) { a2a[i][j][k] = 0; a2b[i][j][k] = 0; }
        const uint32_t db = sb + D_BASE;
        prefetch_chunk(db, 0, T_CH + 0, m0, n0, gt);
        asm volatile("cp.async.commit_group;");
        prefetch_chunk(db, 1, T_CH + 1, m0, n0, gt);
        asm volatile("cp.async.commit_group;");
        prefetch_chunk(db, 2, T_CH + 2, m0, n0, gt);
        asm volatile("cp.async.commit_group;");
        for (int j = 0; j < D_CH; ++j) {
            asm volatile("cp.async.wait_group 2;");
            asm volatile("bar.sync 2, 128;" ::: "memory");
            if (j + 3 < D_CH) prefetch_chunk(db, (j + 3) & 3, T_CH + j + 3, m0, n0, gt);
            asm volatile("cp.async.commit_group;");
            const uint32_t sbase = db + (uint32_t)((j & 3) * CHUNK_BYTES);
            if (T_CH + j < 32) DP4A_CHUNK(a2a, sbase) else DP4A_CHUNK(a2b, sbase)
        }
        asm volatile("cp.async.wait_group 0;");
        asm volatile("bar.sync 2, 128;" ::: "memory");
        // write accumulators to exchange buffer (in dp4a's dead stage region)
        int4* dst = reinterpret_cast<int4*>(exch + (w * 32 + lane) * 68);
#pragma unroll
        for (int mf = 0; mf < 4; ++mf)
#pragma unroll
            for (int nf = 0; nf < 2; ++nf) {
                dst[mf * 2 + nf] = make_int4(a2a[mf][nf][0], a2a[mf][nf][1],
                                             a2a[mf][nf][2], a2a[mf][nf][3]);
                dst[8 + mf * 2 + nf] = make_int4(a2b[mf][nf][0], a2b[mf][nf][1],
                                                 a2b[mf][nf][2], a2b[mf][nf][3]);
            }
    }

    __syncthreads();

    const int u0 = n0 >> 2;                  // 8 hidden units per tile
    // all 256 threads stage cx (tensor region is dead after the join)
#pragma unroll
    for (int t = 0; t < 4; ++t) {
        const int idx = t * 256 + tid;
        const int r = idx >> 3, u = idx & 7;
        cx_sm[r * 9 + u] = cx[(size_t)(m0 + r) * H_DIM + u0 + u];
    }
    __syncthreads();

    if (grp == 0) {
        // combine + fused LSTM epilogue (tensor warps only)
        const int4* src = reinterpret_cast<const int4*>(exch + (w * 32 + lane) * 68);
        const float INV = 1.0f / 16129.0f;           // 1/127^2
        const float INV2 = 5.0f / 4129024.0f;        // 5/(127^2*256)
        const bool oddl = (lane & 1) != 0;
#pragma unroll
        for (int mf = 0; mf < 4; ++mf) {
#pragma unroll
            for (int nf = 0; nf < 2; ++nf) {
                const int4 sa = src[mf * 2 + nf];
                const int4 sbv = src[8 + mf * 2 + nf];
                const int col0 = wn * 16 + nf * 8 + 2 * (lane & 3);
                const float bf0 = g_bias[n0 + col0];
                const float bf1 = g_bias[n0 + col0 + 1];
                float v0 = fmaf((float)(acc1[mf][nf][0] + sa.x), INV,
                           fmaf((float)sbv.x, INV2, bf0));
                float v1 = fmaf((float)(acc1[mf][nf][1] + sa.y), INV,
                           fmaf((float)sbv.y, INV2, bf1));
                float v2 = fmaf((float)(acc1[mf][nf][2] + sa.z), INV,
                           fmaf((float)sbv.z, INV2, bf0));
                float v3 = fmaf((float)(acc1[mf][nf][3] + sa.w), INV,
                           fmaf((float)sbv.w, INV2, bf1));
                float p0 = __shfl_xor_sync(0xFFFFFFFFu, v0, 1);
                float p1 = __shfl_xor_sync(0xFFFFFFFFu, v1, 1);
                float p2 = __shfl_xor_sync(0xFFFFFFFFu, v2, 1);
                float p3 = __shfl_xor_sync(0xFFFFFFFFu, v3, 1);
                const float gf = oddl ? p2 : v0;
                const float gi = oddl ? p3 : v1;
                const float gg = oddl ? v2 : p0;
                const float go = oddl ? v3 : p1;
                const int r = wm * 64 + mf * 16 + (lane >> 2) + (oddl ? 8 : 0);
                const int ul = wn * 4 + nf * 2 + ((lane & 3) >> 1);
                const float f = fq8(sigm_(gf));
                const float ii = fq8(sigm_(gi));
                const float gq = fq8(tanh_(gg));
                const float o = fq8(sigm_(go));
                const float cn = f * cx_sm[r * 9 + ul] + ii * gq;
                h_sm[r * 9 + ul] = o * fq8(tanh_(cn));
                c_sm[r * 9 + ul] = fq8(cn);
            }
        }
    }
    __syncthreads();

    float* hout = out;
    float* cout_ = out + (size_t)B_DIM * H_DIM;
#pragma unroll
    for (int t = 0; t < 4; ++t) {
        const int idx = t * 256 + tid;
        const int r = idx >> 3, u = idx & 7;
        hout[(size_t)(m0 + r) * H_DIM + u0 + u] = h_sm[r * 9 + u];
        cout_[(size_t)(m0 + r) * H_DIM + u0 + u] = c_sm[r * 9 + u];
    }
}

// ------------------------------- launcher ---------------------------------

extern "C" void kernel_launch(void* const* d_in, const int* in_sizes, int n_in,
                              void* d_out, int out_size) {
    (void)in_sizes; (void)n_in; (void)out_size;
    const float* x  = (const float*)d_in[0];
    const float* hx = (const float*)d_in[1];
    const float* cx = (const float*)d_in[2];
    const float* wx = (const float*)d_in[3];
    const float* bx = (const float*)d_in[4];
    const float* wh = (const float*)d_in[5];
    const float* bh = (const float*)d_in[6];
    float* out = (float*)d_out;

    cudaFuncSetAttribute(lstm_imma_kernel,
                         cudaFuncAttributeMaxDynamicSharedMemorySize, SMEM_BYTES);

    prep_A<<<dim3(2, B_DIM), 256>>>(x, hx);
    prep_W<<<dim3(6, NTOT), 256>>>(wx, wh);
    prep_bias<<<NTOT / 256, 256>>>(bx, bh);

    dim3 grid(NTOT / 32, B_DIM / 128);          // 256 x 8 = 2048 CTAs
    lstm_imma_kernel<<<grid, 256, SMEM_BYTES>>>(cx, out);
}